// round 9
// baseline (speedup 1.0000x reference)
#include <cuda_runtime.h>

#define N_VERTS 53215
#define EXP_DIM 29
#define SHP_DIM 199
#define SHP3    (3 * SHP_DIM)   // 597
#define EXP3    (3 * EXP_DIM)   // 87

#define NTHREADS 256
#define N_GROUPS ((N_VERTS + 3) / 4)            // 13304 (last group has 3 verts)
#define NBLOCKS  ((N_GROUPS + 7) / 8)           // 1663

// ---------------------------------------------------------------------------
// Warp-per-4-vertices with LDG.128 streaming.
//
// A 4-vertex shp block = 2388 floats = 597 float4s, 16B-aligned for every
// group (9552 B stride). 19 float4 passes (18 full + 21-lane tail), loaded in
// 3 register batches of 8 (syncwarp-fenced -> front-batched, MLP 8x16B/lane).
// Each 128-float pass window crosses at most ONE 199-boundary (199 > 127), so
// every component routes into one of two compile-time accumulators (12 total:
// 4 verts x 3 rows) via a single predicate.
// Alphas live in smem BANKED as s_a[(col&3)*52 + (col>>2)] so the stride-4
// column pattern becomes two stride-1 runs (<=2-way conflict instead of 4-way,
// which would oversubscribe the smem crossbar).
// Exp part (12.7% of bytes) stays scalar per vertex with compile-time routing.
//
// Transform (derived from _transform_matrix(pose, 450)):
//   s  = p3 + p7 + p11
//   ox = ( s*(p0x + p1y + p2z)  + p3)        * (224/450)
//   oy = (-s*(p4x + p5y + p6z)  - p7 + 450)  * (224/450)
//   oz =   s*(p8x + p9y + p10z)
// ---------------------------------------------------------------------------
__global__ void __launch_bounds__(NTHREADS, 4)
pca_vec_kernel(const float* __restrict__ pose,
               const float* __restrict__ a_exp,
               const float* __restrict__ a_shp,
               const float* __restrict__ u,
               const float* __restrict__ w_exp,
               const float* __restrict__ w_shp,
               float* __restrict__ out)
{
    __shared__ float s_a[256];        // banked shp alphas: s_a[r*52+k] = a_shp[4k+r]
    __shared__ float s_ae[EXP_DIM];   // exp alphas

    const int tid = threadIdx.x;
    {
        const int r   = tid / 52;
        const int k   = tid % 52;
        const int col = 4 * k + r;
        s_a[tid] = (r < 4 && col < SHP_DIM) ? a_shp[col] : 0.0f;  // all 256 slots defined
        if (tid < EXP_DIM) s_ae[tid] = a_exp[tid];
    }
    __syncthreads();

    const int gw   = (blockIdx.x * NTHREADS + tid) >> 5;
    const int lane = tid & 31;
    if (gw >= N_GROUPS) return;

    const int v0 = gw * 4;
    const int nv = (N_VERTS - v0 < 4) ? (N_VERTS - v0) : 4;

    float acc[12];
    #pragma unroll
    for (int i = 0; i < 12; i++) acc[i] = 0.0f;

    if (nv == 4) {
        // ---- fast path: vectorized shp stream ----
        const float4* __restrict__ wsb =
            reinterpret_cast<const float4*>(w_shp) + (size_t)gw * SHP3;  // 597 f4/group

        #pragma unroll
        for (int ch = 0; ch < 3; ch++) {
            const int p0 = ch * 8;
            const int np = (ch == 2) ? 3 : 8;   // passes 0..7, 8..15, 16..18

            float4 b[8];
            #pragma unroll
            for (int q = 0; q < 8; q++) {
                if (q < np) {
                    const int p = p0 + q;
                    const int f = 32 * p + lane;
                    if (p < 18) b[q] = __ldcs(wsb + f);
                    else        b[q] = (lane < 21) ? __ldcs(wsb + f)
                                                   : make_float4(0.f, 0.f, 0.f, 0.f);
                }
            }
            __syncwarp();   // force batched LDG.128 emission

            #pragma unroll
            for (int q = 0; q < 8; q++) {
                if (q < np) {
                    const int p = p0 + q;
                    #pragma unroll
                    for (int c = 0; c < 4; c++) {
                        const int t0     = 128 * p + c;            // compile-time
                        const int s_lo   = t0 / SHP_DIM;
                        const int rem    = t0 - SHP_DIM * s_lo;    // [0,199)
                        const int s_hi   = (s_lo + 1 < 12) ? s_lo + 1 : 11;
                        const int off_lo = (rem & 3) * 52 + (rem >> 2);
                        const int r_hi   = (rem + 1) & 3;
                        const int off_hi = r_hi * 52 + ((rem - SHP_DIM - r_hi) >> 2);

                        const float wv = (c == 0) ? b[q].x : (c == 1) ? b[q].y
                                       : (c == 2) ? b[q].z : b[q].w;
                        const bool hi  = (4 * lane >= SHP_DIM - rem);
                        const int  idx = lane + (hi ? off_hi : off_lo);
                        const float prod = wv * s_a[idx];

                        const bool act = (p < 18) || (lane < 21);
                        if (act) {
                            if (hi) acc[s_hi] += prod;
                            else    acc[s_lo] += prod;
                        }
                    }
                }
            }
        }
    } else {
        // ---- tail group (nv=3): scalar per-vertex shp (R7 style) ----
        #pragma unroll
        for (int k = 0; k < 4; k++) {
            if (k < nv) {
                const float* __restrict__ ws = w_shp + (size_t)(v0 + k) * SHP3;
                #pragma unroll
                for (int i = 0; i < 19; i++) {
                    const int j = 32 * i + lane;
                    if (j < SHP3) {
                        int col, row;
                        if (j < SHP_DIM)          { col = j;               row = 0; }
                        else if (j < 2 * SHP_DIM) { col = j - SHP_DIM;     row = 1; }
                        else                      { col = j - 2 * SHP_DIM; row = 2; }
                        const float av = s_a[(col & 3) * 52 + (col >> 2)];
                        const float p  = ws[j] * av;
                        if (row == 0)      acc[3 * k + 0] += p;
                        else if (row == 1) acc[3 * k + 1] += p;
                        else               acc[3 * k + 2] += p;
                    }
                }
            }
        }
    }

    // ---- exp part: scalar per vertex, compile-time routing ----
    {
        const float* __restrict__ web = w_exp + (size_t)v0 * EXP3;
        #pragma unroll
        for (int k = 0; k < 4; k++) {
            if (k < nv) {
                #pragma unroll
                for (int i = 0; i < 3; i++) {
                    const int j = 32 * i + lane;
                    if (j < EXP3) {
                        int col, row;
                        if (j < EXP_DIM)          { col = j;               row = 0; }
                        else if (j < 2 * EXP_DIM) { col = j - EXP_DIM;     row = 1; }
                        else                      { col = j - 2 * EXP_DIM; row = 2; }
                        const float p = __ldcs(web + k * EXP3 + j) * s_ae[col];
                        if (row == 0)      acc[3 * k + 0] += p;
                        else if (row == 1) acc[3 * k + 1] += p;
                        else               acc[3 * k + 2] += p;
                    }
                }
            }
        }
    }

    // ---- warp reductions (12 values) ----
    #pragma unroll
    for (int off = 16; off > 0; off >>= 1) {
        #pragma unroll
        for (int i = 0; i < 12; i++)
            acc[i] += __shfl_down_sync(0xffffffffu, acc[i], off);
    }

    // ---- transform + store (lane 0) ----
    if (lane == 0) {
        const float p0 = __ldg(pose + 0),  p1 = __ldg(pose + 1),  p2  = __ldg(pose + 2),  p3  = __ldg(pose + 3);
        const float p4 = __ldg(pose + 4),  p5 = __ldg(pose + 5),  p6  = __ldg(pose + 6),  p7  = __ldg(pose + 7);
        const float p8 = __ldg(pose + 8),  p9 = __ldg(pose + 9),  p10 = __ldg(pose + 10), p11 = __ldg(pose + 11);
        const float s  = p3 + p7 + p11;
        const float aspect_xy = 224.0f / 450.0f;

        #pragma unroll
        for (int k = 0; k < 4; k++) {
            if (k < nv) {
                const int v = v0 + k;
                const float x = acc[3 * k + 0] + __ldg(u + 3 * v + 0);
                const float y = acc[3 * k + 1] + __ldg(u + 3 * v + 1);
                const float z = acc[3 * k + 2] + __ldg(u + 3 * v + 2);
                out[3 * v + 0] = ( s * (p0 * x + p1 * y + p2  * z) + p3)          * aspect_xy;
                out[3 * v + 1] = (-s * (p4 * x + p5 * y + p6  * z) - p7 + 450.0f) * aspect_xy;
                out[3 * v + 2] =   s * (p8 * x + p9 * y + p10 * z);
            }
        }
    }
}

// ---------------------------------------------------------------------------
// Entry point
// Input order: pose_3DMM, alpha_exp, alpha_shp, u_base, w_exp_base, w_shp_base
// ---------------------------------------------------------------------------
extern "C" void kernel_launch(void* const* d_in, const int* in_sizes, int n_in,
                              void* d_out, int out_size)
{
    const float* pose  = (const float*)d_in[0];
    const float* a_exp = (const float*)d_in[1];
    const float* a_shp = (const float*)d_in[2];
    const float* u     = (const float*)d_in[3];
    const float* w_exp = (const float*)d_in[4];
    const float* w_shp = (const float*)d_in[5];
    float* out = (float*)d_out;

    pca_vec_kernel<<<NBLOCKS, NTHREADS>>>(pose, a_exp, a_shp, u, w_exp, w_shp, out);
}

// round 10
// speedup vs baseline: 1.1866x; 1.1866x over previous
#include <cuda_runtime.h>

#define N_VERTS 53215
#define EXP_DIM 29
#define SHP_DIM 199
#define SHP3    (3 * SHP_DIM)   // 597
#define EXP3    (3 * EXP_DIM)   // 87
#define ADIM    (SHP_DIM + EXP_DIM)  // 228

#define NTHREADS 256
#define WARPS_PER_BLOCK (NTHREADS / 32)

// ---------------------------------------------------------------------------
// R2 skeleton (warp-per-vertex, 6652 blocks, lean registers, high occupancy)
// + alphas in shared memory (halves LDG warp-instructions: 44 -> 22/vertex).
//
// Rationale (budget per SM per pass): DRAM floor ~23.2K cyc; R2/R7 issued
// 44 LDG/vertex -> 28.8K LSU cyc (binding). Moving the 22 alpha reads to the
// smem port drops LSU to ~14.4K cyc, making DRAM the binding resource.
// No forced register batching (that cost occupancy in R7/R8); ptxas
// software-pipelines the stream at ~6 blocks/SM residency.
//
// Transform (derived from _transform_matrix(pose, 450)):
//   s  = p3 + p7 + p11
//   ox = ( s*(p0x + p1y + p2z)  + p3)        * (224/450)
//   oy = (-s*(p4x + p5y + p6z)  - p7 + 450)  * (224/450)
//   oz =   s*(p8x + p9y + p10z)
// ---------------------------------------------------------------------------
__global__ void __launch_bounds__(NTHREADS, 6)
pca_lean_kernel(const float* __restrict__ pose,
                const float* __restrict__ a_exp,
                const float* __restrict__ a_shp,
                const float* __restrict__ u,
                const float* __restrict__ w_exp,
                const float* __restrict__ w_shp,
                float* __restrict__ out)
{
    __shared__ float s_a[ADIM];   // [0..198] = a_shp, [199..227] = a_exp

    const int t = threadIdx.x;
    if (t < ADIM)
        s_a[t] = (t < SHP_DIM) ? a_shp[t] : a_exp[t - SHP_DIM];
    __syncthreads();

    const int warp = (blockIdx.x * blockDim.x + t) >> 5;
    const int lane = t & 31;
    if (warp >= N_VERTS) return;

    const float* __restrict__ ws = w_shp + (size_t)warp * SHP3;
    const float* __restrict__ we = w_exp + (size_t)warp * EXP3;

    float a0 = 0.f, a1 = 0.f, a2 = 0.f;

    // ---- SHP: 597 contiguous floats, 19 coalesced passes ----
    #pragma unroll
    for (int i = 0; i < 19; i++) {
        const int j = i * 32 + lane;
        if (j < SHP3) {
            int col;
            if (j < SHP_DIM)          col = j;
            else if (j < 2 * SHP_DIM) col = j - SHP_DIM;
            else                      col = j - 2 * SHP_DIM;
            const float p = __ldcs(ws + j) * s_a[col];
            if (j < SHP_DIM)          a0 += p;
            else if (j < 2 * SHP_DIM) a1 += p;
            else                      a2 += p;
        }
    }

    // ---- EXP: 87 contiguous floats, 3 coalesced passes ----
    #pragma unroll
    for (int i = 0; i < 3; i++) {
        const int j = i * 32 + lane;
        if (j < EXP3) {
            int col;
            if (j < EXP_DIM)          col = j;
            else if (j < 2 * EXP_DIM) col = j - EXP_DIM;
            else                      col = j - 2 * EXP_DIM;
            const float p = __ldcs(we + j) * s_a[SHP_DIM + col];
            if (j < EXP_DIM)          a0 += p;
            else if (j < 2 * EXP_DIM) a1 += p;
            else                      a2 += p;
        }
    }

    // ---- warp reductions (3 values) ----
    #pragma unroll
    for (int off = 16; off > 0; off >>= 1) {
        a0 += __shfl_down_sync(0xffffffffu, a0, off);
        a1 += __shfl_down_sync(0xffffffffu, a1, off);
        a2 += __shfl_down_sync(0xffffffffu, a2, off);
    }

    if (lane == 0) {
        const float p0 = __ldg(pose + 0),  p1 = __ldg(pose + 1),  p2  = __ldg(pose + 2),  p3  = __ldg(pose + 3);
        const float p4 = __ldg(pose + 4),  p5 = __ldg(pose + 5),  p6  = __ldg(pose + 6),  p7  = __ldg(pose + 7);
        const float p8 = __ldg(pose + 8),  p9 = __ldg(pose + 9),  p10 = __ldg(pose + 10), p11 = __ldg(pose + 11);
        const float s  = p3 + p7 + p11;
        const float aspect_xy = 224.0f / 450.0f;

        const float x = a0 + __ldg(u + 3 * warp + 0);
        const float y = a1 + __ldg(u + 3 * warp + 1);
        const float z = a2 + __ldg(u + 3 * warp + 2);

        out[3 * warp + 0] = ( s * (p0 * x + p1 * y + p2  * z) + p3)          * aspect_xy;
        out[3 * warp + 1] = (-s * (p4 * x + p5 * y + p6  * z) - p7 + 450.0f) * aspect_xy;
        out[3 * warp + 2] =   s * (p8 * x + p9 * y + p10 * z);
    }
}

// ---------------------------------------------------------------------------
// Entry point
// Input order: pose_3DMM, alpha_exp, alpha_shp, u_base, w_exp_base, w_shp_base
// ---------------------------------------------------------------------------
extern "C" void kernel_launch(void* const* d_in, const int* in_sizes, int n_in,
                              void* d_out, int out_size)
{
    const float* pose  = (const float*)d_in[0];
    const float* a_exp = (const float*)d_in[1];
    const float* a_shp = (const float*)d_in[2];
    const float* u     = (const float*)d_in[3];
    const float* w_exp = (const float*)d_in[4];
    const float* w_shp = (const float*)d_in[5];
    float* out = (float*)d_out;

    const int blocks = (N_VERTS + WARPS_PER_BLOCK - 1) / WARPS_PER_BLOCK;
    pca_lean_kernel<<<blocks, NTHREADS>>>(pose, a_exp, a_shp, u, w_exp, w_shp, out);
}